// round 7
// baseline (speedup 1.0000x reference)
#include <cuda_runtime.h>
#include <cuda_bf16.h>

// SurvivalGeometryRegularizer:
//   mask[i][j] = (time[i] < time[j]) && (event[i] == 1)
//   hinge      = relu(1 + risk[i] - risk[j])
//   out        = sum(mask*hinge) / sum(mask)   (0 if count==0)
// z (d_in[0]) is UNUSED. Inputs: [1]=risk f32[B], [2]=time f32[B], [3]=event i32[B].
//
// R7: occupancy round. R6 showed issue=71% @ occ=39% (6 warps/SMSP) with the
// instruction model already tight -> issue-slot starvation, not instr bloat.
// Fix: 74 x 16 = 1184 blocks = exactly 8 blocks/SM on 148 SMs, one full wave,
// __launch_bounds__(256,8) (regs<=32). JPT=2 keeps register use ~20.
//   - per-block smem compaction of event rows (2x work cut), INF sentinel pad
//   - inner loop: broadcast LDS.64 + 2x (FADD, FMNMX, setp, @p add, @p add)
//   - last-block ticket finalize, fixed-order sums -> bitwise deterministic.

#define BNUM   8192
#define TPB    256
#define ISPLIT 74
#define JSPLIT 16
#define JPT    2
#define JTILE  (TPB * JPT)        // 512
#define NPART  (ISPLIT * JSPLIT)  // 1184 blocks = 8/SM * 148 SMs
#define MAXROW 128                // >= 111 rows + 8 pad

__device__ float        g_ps[NPART];
__device__ float        g_pc[NPART];
__device__ unsigned int g_ticket;   // zero-init at load; last block resets to 0

__global__ __launch_bounds__(TPB, 8) void fused_pair_kernel(
    const float* __restrict__ risk,
    const float* __restrict__ time_,
    const int*   __restrict__ event,
    float*       __restrict__ out)
{
    __shared__ float2    s_i[MAXROW];      // compacted (t_i, 1+r_i), INF-padded
    __shared__ int       s_wsum[TPB / 32];
    __shared__ int       s_lne;
    __shared__ float     s_rs[TPB / 32];
    __shared__ float     s_rc[TPB / 32];
    __shared__ int       s_islast;
    __shared__ double    f_s[TPB / 32];
    __shared__ double    f_c[TPB / 32];

    const int tid  = threadIdx.x;
    const int lane = tid & 31;
    const int wid  = tid >> 5;
    const int bid  = blockIdx.y * ISPLIT + blockIdx.x;

    // ---- this block's i-range (balanced split of 8192 over 74) ----------
    const int ilo  = (blockIdx.x * BNUM) / ISPLIT;
    const int ihi  = ((blockIdx.x + 1) * BNUM) / ISPLIT;
    const int rows = ihi - ilo;             // 110 or 111

    const int   inr = tid < rows;
    const int   i   = ilo + tid;
    const int   ev  = inr ? event[i] : 0;
    const float tiv = inr ? time_[i] : 0.0f;
    const float aiv = inr ? (1.0f + risk[i]) : 0.0f;

    // ---- this thread's 2 j-columns (coalesced) ---------------------------
    const int j0 = blockIdx.y * JTILE;
    float tj[JPT], nrj[JPT];
    #pragma unroll
    for (int m = 0; m < JPT; m++) {
        const int j = j0 + m * TPB + tid;
        tj[m]  = time_[j];
        nrj[m] = -risk[j];
    }

    // ---- intra-block compaction of event rows into smem ------------------
    int incl = ev;
    #pragma unroll
    for (int off = 1; off < 32; off <<= 1) {
        int y = __shfl_up_sync(0xffffffffu, incl, off);
        if (lane >= off) incl += y;
    }
    if (lane == 31) s_wsum[wid] = incl;
    __syncthreads();

    if (wid == 0) {
        int v = (lane < TPB / 32) ? s_wsum[lane] : 0;
        #pragma unroll
        for (int off = 1; off < TPB / 32; off <<= 1) {
            int y = __shfl_up_sync(0xffffffffu, v, off);
            if (lane >= off) v += y;
        }
        if (lane < TPB / 32) s_wsum[lane] = v;
        if (lane == TPB / 32 - 1) s_lne = v;
    }
    __syncthreads();

    {
        const int base = (wid ? s_wsum[wid - 1] : 0) + (incl - ev);
        if (ev) s_i[base] = make_float2(tiv, aiv);
    }
    __syncthreads();

    const int lne     = s_lne;                     // ~55 event rows
    const int lne_pad = (lne + 7) & ~7;            // multiple of 8, <= 118

    // sentinel pad: t=+INF => setp.lt false => zero contribution
    if (tid < lne_pad - lne)
        s_i[lne + tid] = make_float2(__int_as_float(0x7f800000), 0.0f);
    __syncthreads();

    // ---- main pairwise loop: predicated, branch-free ---------------------
    float s[JPT], c[JPT];
    #pragma unroll
    for (int m = 0; m < JPT; m++) { s[m] = 0.0f; c[m] = 0.0f; }

    for (int k = 0; k < lne_pad; k += 8) {
        #pragma unroll
        for (int u = 0; u < 8; u++) {
            const float2 v = s_i[k + u];          // broadcast LDS.64
            #pragma unroll
            for (int m = 0; m < JPT; m++) {
                const float h = fmaxf(v.y + nrj[m], 0.0f);  // FADD + FMNMX
                asm(
                    "{\n\t"
                    ".reg .pred p;\n\t"
                    "setp.lt.f32 p, %2, %3;\n\t"          // t_i < t_j
                    "@p add.f32 %0, %0, %4;\n\t"          // s += h
                    "@p add.f32 %1, %1, 0f3F800000;\n\t"  // c += 1.0
                    "}"
                    : "+f"(s[m]), "+f"(c[m])
                    : "f"(v.x), "f"(tj[m]), "f"(h));
            }
        }
    }

    float ss = s[0] + s[1];
    float cc = c[0] + c[1];

    // ---- deterministic intra-block reduction -----------------------------
    #pragma unroll
    for (int off = 16; off > 0; off >>= 1) {
        ss += __shfl_down_sync(0xffffffffu, ss, off);
        cc += __shfl_down_sync(0xffffffffu, cc, off);
    }
    if (lane == 0) { s_rs[wid] = ss; s_rc[wid] = cc; }
    __syncthreads();

    if (tid == 0) {
        float sv = 0.0f, cv = 0.0f;
        #pragma unroll
        for (int w = 0; w < TPB / 32; w++) { sv += s_rs[w]; cv += s_rc[w]; }
        g_ps[bid] = sv;
        g_pc[bid] = cv;
    }

    // ---- last-block fused finalize (threadfence + ticket) ----------------
    __threadfence();
    if (tid == 0) {
        const unsigned t = atomicAdd(&g_ticket, 1u);
        s_islast = (t == NPART - 1) ? 1 : 0;
    }
    __syncthreads();

    if (s_islast) {
        __threadfence();                   // all partials now visible
        double sv = 0.0, cv = 0.0;
        for (int idx = tid; idx < NPART; idx += TPB) {   // fixed order
            sv += (double)g_ps[idx];
            cv += (double)g_pc[idx];
        }
        #pragma unroll
        for (int off = 16; off > 0; off >>= 1) {
            sv += __shfl_down_sync(0xffffffffu, sv, off);
            cv += __shfl_down_sync(0xffffffffu, cv, off);
        }
        if (lane == 0) { f_s[wid] = sv; f_c[wid] = cv; }
        __syncthreads();
        if (tid == 0) {
            double ts = 0.0, tc = 0.0;
            #pragma unroll
            for (int w = 0; w < TPB / 32; w++) { ts += f_s[w]; tc += f_c[w]; }
            out[0] = (tc != 0.0) ? (float)(ts / tc) : 0.0f;
            g_ticket = 0;                  // reset for next graph replay
        }
    }
}

extern "C" void kernel_launch(void* const* d_in, const int* in_sizes, int n_in,
                              void* d_out, int out_size)
{
    // d_in[0] = z (unused)
    const float* risk  = (const float*)d_in[1];
    const float* time_ = (const float*)d_in[2];
    const int*   event = (const int*)d_in[3];

    dim3 grid(ISPLIT, JSPLIT);
    fused_pair_kernel<<<grid, TPB>>>(risk, time_, event, (float*)d_out);
}